// round 2
// baseline (speedup 1.0000x reference)
#include <cuda_runtime.h>
#include <cstdint>

// ---------------- problem dims ----------------
#define Bb   8
#define Tt   4
#define Nn   256
#define Dd   512
#define Hh   8
#define DHh  64
#define HIDd 2048
#define BTN  (Bb*Tt*Nn)            // 8192 rows
#define BTND ((size_t)BTN*Dd)      // 4194304
#define SCORES_ELEMS ((size_t)Bb*Tt*Hh*Nn*Nn)  // 16777216
#define HID_ELEMS    ((size_t)BTN*HIDd)        // 16777216

#define BETA 0.95122942450071403f  // fp32(exp(-1/20))

// ---------------- scratch (static device globals; no allocation) ----------------
__device__ float g_s1[BTND];
__device__ float g_q [BTND];
__device__ float g_k [BTND];
__device__ float g_v [BTND];
__device__ float g_scores[SCORES_ELEMS];
__device__ float g_attnout[BTND];
__device__ float g_xmid[BTND];
__device__ float g_s2[BTND];
__device__ float g_hid[HID_ELEMS];
__device__ unsigned long long g_cnt[4];

// ---------------- counters ----------------
__global__ void zero_cnt_kernel() {
    if (threadIdx.x < 4) g_cnt[threadIdx.x] = 0ULL;
}

// ---------------- LayerNorm + LIF over time (per (b,n) row) ----------------
// grid = B*N blocks, 512 threads (one per d). T=4 sequential steps, LIF state in reg.
__global__ void ln_lif_kernel(const float* __restrict__ x,
                              const float* __restrict__ g,
                              const float* __restrict__ bia,
                              float* __restrict__ sp,
                              unsigned long long* __restrict__ counter) {
    __shared__ float red[512];
    int bn = blockIdx.x;
    int b  = bn / Nn, n = bn % Nn;
    int d  = threadIdx.x;
    float gg = g[d], bb = bia[d];
    float mem = 0.f;
    float cnt = 0.f;
    for (int t = 0; t < Tt; ++t) {
        size_t rowoff = ((((size_t)b*Tt + t)*Nn) + n)*Dd;
        float v = x[rowoff + d];
        red[d] = v; __syncthreads();
        #pragma unroll
        for (int off = 256; off > 0; off >>= 1) { if (d < off) red[d] += red[d+off]; __syncthreads(); }
        float mean = red[0] * (1.f/Dd);
        __syncthreads();
        float diff = v - mean;
        red[d] = diff*diff; __syncthreads();
        #pragma unroll
        for (int off = 256; off > 0; off >>= 1) { if (d < off) red[d] += red[d+off]; __syncthreads(); }
        float var = red[0] * (1.f/Dd);
        __syncthreads();
        float h = diff * rsqrtf(var + 1e-5f) * gg + bb;
        mem = BETA*mem + h;
        float s = (mem >= 1.0f) ? 1.f : 0.f;
        mem -= s;                       // thr = 1
        sp[rowoff + d] = s;
        cnt += s;
    }
    red[d] = cnt; __syncthreads();
    #pragma unroll
    for (int off = 256; off > 0; off >>= 1) { if (d < off) red[d] += red[d+off]; __syncthreads(); }
    if (d == 0) atomicAdd(counter, (unsigned long long)(red[0] + 0.5f));
}

// ---------------- generic SGEMM: C = alpha*A@B (+R)  (row-major, contiguous) ----------------
// 64x64 tile, BK=16, 256 threads, 4x4 per thread. Requires M%64==0, N%64==0, K%16==0.
__global__ void sgemm_kernel(const float* __restrict__ A, const float* __restrict__ B,
                             const float* __restrict__ R, float* __restrict__ C,
                             int M, int N, int K, float alpha) {
    __shared__ float As[16][64];
    __shared__ float Bs[16][64];
    int tid = threadIdx.x;
    int bm = blockIdx.y * 64;
    int bn = blockIdx.x * 64;
    int tx = tid & 15, ty = tid >> 4;
    int arow = tid >> 2,  acol = (tid & 3)  << 2;
    int brow = tid >> 4,  bcol = (tid & 15) << 2;
    float acc[4][4] = {};
    for (int k0 = 0; k0 < K; k0 += 16) {
        float4 a = *(const float4*)(A + (size_t)(bm + arow)*K + k0 + acol);
        As[acol+0][arow] = a.x; As[acol+1][arow] = a.y;
        As[acol+2][arow] = a.z; As[acol+3][arow] = a.w;
        *(float4*)&Bs[brow][bcol] = *(const float4*)(B + (size_t)(k0 + brow)*N + bn + bcol);
        __syncthreads();
        #pragma unroll
        for (int kk = 0; kk < 16; ++kk) {
            float4 av = *(const float4*)&As[kk][ty << 2];
            float4 bv = *(const float4*)&Bs[kk][tx << 2];
            float aa[4] = {av.x, av.y, av.z, av.w};
            float bb4[4] = {bv.x, bv.y, bv.z, bv.w};
            #pragma unroll
            for (int i = 0; i < 4; i++)
                #pragma unroll
                for (int j = 0; j < 4; j++) acc[i][j] += aa[i]*bb4[j];
        }
        __syncthreads();
    }
    #pragma unroll
    for (int i = 0; i < 4; i++) {
        int r = bm + (ty << 2) + i;
        #pragma unroll
        for (int j = 0; j < 4; j++) {
            int c = bn + (tx << 2) + j;
            float val = acc[i][j]*alpha;
            if (R) val += R[(size_t)r*N + c];
            C[(size_t)r*N + c] = val;
        }
    }
}

// ---------------- scores[b,t,h,n,m] = 0.125 * sum_d q[bt,n,h,d]*k[bt,m,h,d] ----------------
// grid (N/64, N/64, B*T*H), 256 threads
__global__ void scores_kernel(const float* __restrict__ q, const float* __restrict__ k,
                              float* __restrict__ sc) {
    __shared__ float As[16][64];
    __shared__ float Bs[16][64];
    int bz = blockIdx.z;
    int h = bz % Hh; int bt = bz / Hh;
    const float* qb = q + (size_t)bt*Nn*Dd + h*DHh;
    const float* kb = k + (size_t)bt*Nn*Dd + h*DHh;
    float* cb = sc + (size_t)bz*Nn*Nn;
    int tid = threadIdx.x;
    int n0 = blockIdx.y * 64;
    int m0 = blockIdx.x * 64;
    int tx = tid & 15, ty = tid >> 4;
    int lrow = tid >> 2, lcol = (tid & 3) << 2;
    float acc[4][4] = {};
    for (int d0 = 0; d0 < DHh; d0 += 16) {
        float4 a = *(const float4*)(qb + (size_t)(n0 + lrow)*Dd + d0 + lcol);
        As[lcol+0][lrow] = a.x; As[lcol+1][lrow] = a.y;
        As[lcol+2][lrow] = a.z; As[lcol+3][lrow] = a.w;
        float4 b4 = *(const float4*)(kb + (size_t)(m0 + lrow)*Dd + d0 + lcol);
        Bs[lcol+0][lrow] = b4.x; Bs[lcol+1][lrow] = b4.y;
        Bs[lcol+2][lrow] = b4.z; Bs[lcol+3][lrow] = b4.w;
        __syncthreads();
        #pragma unroll
        for (int kk = 0; kk < 16; ++kk) {
            float4 av = *(const float4*)&As[kk][ty << 2];
            float4 bv = *(const float4*)&Bs[kk][tx << 2];
            float aa[4] = {av.x, av.y, av.z, av.w};
            float bb4[4] = {bv.x, bv.y, bv.z, bv.w};
            #pragma unroll
            for (int i = 0; i < 4; i++)
                #pragma unroll
                for (int j = 0; j < 4; j++) acc[i][j] += aa[i]*bb4[j];
        }
        __syncthreads();
    }
    #pragma unroll
    for (int i = 0; i < 4; i++) {
        int r = n0 + (ty << 2) + i;
        #pragma unroll
        for (int j = 0; j < 4; j++) {
            int c = m0 + (tx << 2) + j;
            cb[(size_t)r*Nn + c] = acc[i][j]*0.125f;
        }
    }
}

// ---------------- out[bt,n,h,dh] = sum_m sa[b,t,h,n,m]*v[bt,m,h,dh] ----------------
// grid (1, N/64, B*T*H), 256 threads
__global__ void attnout_kernel(const float* __restrict__ sa, const float* __restrict__ v,
                               float* __restrict__ outp) {
    __shared__ float As[16][64];  // [m_k][n]
    __shared__ float Bs[16][64];  // [m_k][dh]
    int bz = blockIdx.z;
    int h = bz % Hh; int bt = bz / Hh;
    const float* ab = sa + (size_t)bz*Nn*Nn;
    const float* vb = v + (size_t)bt*Nn*Dd + h*DHh;
    float* cb = outp + (size_t)bt*Nn*Dd + h*DHh;
    int n0 = blockIdx.y * 64;
    int tid = threadIdx.x;
    int tx = tid & 15, ty = tid >> 4;
    int arow = tid >> 2,  acol = (tid & 3)  << 2;
    int brow = tid >> 4,  bcol = (tid & 15) << 2;
    float acc[4][4] = {};
    for (int m0 = 0; m0 < Nn; m0 += 16) {
        float4 a = *(const float4*)(ab + (size_t)(n0 + arow)*Nn + m0 + acol);
        As[acol+0][arow] = a.x; As[acol+1][arow] = a.y;
        As[acol+2][arow] = a.z; As[acol+3][arow] = a.w;
        *(float4*)&Bs[brow][bcol] = *(const float4*)(vb + (size_t)(m0 + brow)*Dd + bcol);
        __syncthreads();
        #pragma unroll
        for (int kk = 0; kk < 16; ++kk) {
            float4 av = *(const float4*)&As[kk][ty << 2];
            float4 bv = *(const float4*)&Bs[kk][tx << 2];
            float aa[4] = {av.x, av.y, av.z, av.w};
            float bb4[4] = {bv.x, bv.y, bv.z, bv.w};
            #pragma unroll
            for (int i = 0; i < 4; i++)
                #pragma unroll
                for (int j = 0; j < 4; j++) acc[i][j] += aa[i]*bb4[j];
        }
        __syncthreads();
    }
    #pragma unroll
    for (int i = 0; i < 4; i++) {
        int r = n0 + (ty << 2) + i;
        #pragma unroll
        for (int j = 0; j < 4; j++) {
            cb[(size_t)r*Dd + (tx << 2) + j] = acc[i][j];
        }
    }
}

// ---------------- in-place LIF over time axis (t stride = inner) ----------------
// data layout (Bb, T, inner); recurrence per (b, r) over t. Spikes overwrite data.
__global__ void lif_time_kernel(float* __restrict__ data, int inner_sz, float thr,
                                unsigned long long* __restrict__ counter) {
    long long total = (long long)Bb * inner_sz;
    long long idx = (long long)blockIdx.x*blockDim.x + threadIdx.x;
    int cnt = 0;
    if (idx < total) {
        long long b = idx / inner_sz, r = idx % inner_sz;
        float* p = data + (size_t)b*Tt*inner_sz + r;
        float mem = 0.f;
        #pragma unroll
        for (int t = 0; t < Tt; ++t) {
            float v2 = p[(size_t)t*inner_sz];
            mem = BETA*mem + v2;
            float s = (mem >= thr) ? 1.f : 0.f;
            p[(size_t)t*inner_sz] = s;
            mem -= s*thr;
            cnt += (int)s;
        }
    }
    #pragma unroll
    for (int off = 16; off; off >>= 1) cnt += __shfl_down_sync(0xffffffffu, cnt, off);
    if ((threadIdx.x & 31) == 0 && cnt) atomicAdd(counter, (unsigned long long)cnt);
}

// ---------------- write the 4 spike-rate scalars ----------------
__global__ void finalize_kernel(float* __restrict__ out, long long out_size) {
    if (out_size >= (long long)BTND + 4) {
        out[BTND+0] = (float)((double)g_cnt[0] / 4194304.0);   // r_lif1
        out[BTND+1] = (float)((double)g_cnt[1] / 16777216.0);  // r_attn
        out[BTND+2] = (float)((double)g_cnt[2] / 4194304.0);   // r_lif2
        out[BTND+3] = (float)((double)g_cnt[3] / 16777216.0);  // r_ffn
    }
}

// ---------------- host launcher ----------------
extern "C" void kernel_launch(void* const* d_in, const int* in_sizes, int n_in,
                              void* d_out, int out_size) {
    const float* x  = (const float*)d_in[0];
    const float* g1 = (const float*)d_in[1];
    const float* b1 = (const float*)d_in[2];
    const float* wq = (const float*)d_in[3];
    const float* wk = (const float*)d_in[4];
    const float* wv = (const float*)d_in[5];
    const float* wo = (const float*)d_in[6];
    const float* g2 = (const float*)d_in[7];
    const float* b2 = (const float*)d_in[8];
    const float* w1 = (const float*)d_in[9];
    const float* w2 = (const float*)d_in[10];
    float* out = (float*)d_out;

    float *s1, *q, *k, *v, *sc, *ao, *xm, *s2, *hid;
    unsigned long long* cnt;
    cudaGetSymbolAddress((void**)&s1,  g_s1);
    cudaGetSymbolAddress((void**)&q,   g_q);
    cudaGetSymbolAddress((void**)&k,   g_k);
    cudaGetSymbolAddress((void**)&v,   g_v);
    cudaGetSymbolAddress((void**)&sc,  g_scores);
    cudaGetSymbolAddress((void**)&ao,  g_attnout);
    cudaGetSymbolAddress((void**)&xm,  g_xmid);
    cudaGetSymbolAddress((void**)&s2,  g_s2);
    cudaGetSymbolAddress((void**)&hid, g_hid);
    cudaGetSymbolAddress((void**)&cnt, g_cnt);

    dim3 thr(256);

    zero_cnt_kernel<<<1, 32>>>();

    // attention branch
    ln_lif_kernel<<<Bb*Nn, 512>>>(x, g1, b1, s1, cnt + 0);
    sgemm_kernel<<<dim3(Dd/64,  BTN/64), thr>>>(s1, wq, nullptr, q, BTN, Dd, Dd, 1.f);
    sgemm_kernel<<<dim3(Dd/64,  BTN/64), thr>>>(s1, wk, nullptr, k, BTN, Dd, Dd, 1.f);
    sgemm_kernel<<<dim3(Dd/64,  BTN/64), thr>>>(s1, wv, nullptr, v, BTN, Dd, Dd, 1.f);
    scores_kernel<<<dim3(Nn/64, Nn/64, Bb*Tt*Hh), thr>>>(q, k, sc);
    lif_time_kernel<<<16384, 256>>>(sc, Hh*Nn*Nn, 0.5f, cnt + 1);
    attnout_kernel<<<dim3(1, Nn/64, Bb*Tt*Hh), thr>>>(sc, v, ao);
    sgemm_kernel<<<dim3(Dd/64,  BTN/64), thr>>>(ao, wo, x, xm, BTN, Dd, Dd, 1.f);

    // MLP branch
    ln_lif_kernel<<<Bb*Nn, 512>>>(xm, g2, b2, s2, cnt + 2);
    sgemm_kernel<<<dim3(HIDd/64, BTN/64), thr>>>(s2, w1, nullptr, hid, BTN, HIDd, Dd, 1.f);
    lif_time_kernel<<<16384, 256>>>(hid, Nn*HIDd, 1.0f, cnt + 3);
    sgemm_kernel<<<dim3(Dd/64,  BTN/64), thr>>>(hid, w2, xm, out, BTN, Dd, HIDd, 1.f);

    finalize_kernel<<<1, 1>>>(out, (long long)out_size);
}

// round 4
// speedup vs baseline: 2.5158x; 2.5158x over previous
#include <cuda_runtime.h>
#include <cuda_fp16.h>
#include <cstdint>

// ---------------- problem dims ----------------
#define Bb   8
#define Tt   4
#define Nn   256
#define Dd   512
#define Hh   8
#define DHh  64
#define HIDd 2048
#define BTN  (Bb*Tt*Nn)            // 8192 rows
#define BTND ((size_t)BTN*Dd)      // 4194304
#define SCORES_ELEMS ((size_t)Bb*Tt*Hh*Nn*Nn)  // 16777216
#define HID_ELEMS    ((size_t)BTN*HIDd)        // 16777216

#define BETA 0.95122942450071403f  // fp32(exp(-1/20))
#define LOSCALE 2048.0f
#define INV_LOSCALE (1.0f/2048.0f)

// ---------------- scratch (static device globals; no allocation) ----------------
__device__ __half g_s1h[BTND];
__device__ __half g_qh[BTND], g_ql[BTND];
__device__ __half g_kh[BTND], g_kl[BTND];
__device__ __half g_vh[BTND], g_vl[BTND];
__device__ float  g_scores[SCORES_ELEMS];
__device__ __half g_sah[SCORES_ELEMS];
__device__ __half g_aoh[BTND], g_aol[BTND];
__device__ float  g_xm[BTND];
__device__ __half g_s2h[BTND];
__device__ float  g_hid[HID_ELEMS];
__device__ __half g_hsh[HID_ELEMS];
// weight splits
__device__ __half g_wqh[Dd*Dd], g_wql[Dd*Dd];
__device__ __half g_wkh[Dd*Dd], g_wkl[Dd*Dd];
__device__ __half g_wvh[Dd*Dd], g_wvl[Dd*Dd];
__device__ __half g_woh[Dd*Dd], g_wol[Dd*Dd];
__device__ __half g_w1h[Dd*HIDd], g_w1l[Dd*HIDd];
__device__ __half g_w2h[HIDd*Dd], g_w2l[HIDd*Dd];
__device__ unsigned long long g_cnt[4];

// ---------------- small helpers ----------------
__global__ void zero_cnt_kernel() {
    if (threadIdx.x < 4) g_cnt[threadIdx.x] = 0ULL;
}

__global__ void split_kernel(const float* __restrict__ src,
                             __half* __restrict__ hi, __half* __restrict__ lo, int n) {
    int i = blockIdx.x*blockDim.x + threadIdx.x;
    if (i < n) {
        float v = src[i];
        __half h = __float2half_rn(v);
        hi[i] = h;
        lo[i] = __float2half_rn((v - __half2float(h)) * LOSCALE);
    }
}

// ---------------- LayerNorm + LIF over time (per (b,n) row) ----------------
__global__ void ln_lif_kernel(const float* __restrict__ x,
                              const float* __restrict__ g,
                              const float* __restrict__ bia,
                              __half* __restrict__ sp,
                              unsigned long long* __restrict__ counter) {
    __shared__ float red[512];
    int bn = blockIdx.x;
    int b  = bn / Nn, n = bn % Nn;
    int d  = threadIdx.x;
    float gg = g[d], bb = bia[d];
    float mem = 0.f;
    float cnt = 0.f;
    for (int t = 0; t < Tt; ++t) {
        size_t rowoff = ((((size_t)b*Tt + t)*Nn) + n)*Dd;
        float v = x[rowoff + d];
        red[d] = v; __syncthreads();
        #pragma unroll
        for (int off = 256; off > 0; off >>= 1) { if (d < off) red[d] += red[d+off]; __syncthreads(); }
        float mean = red[0] * (1.f/Dd);
        __syncthreads();
        float diff = v - mean;
        red[d] = diff*diff; __syncthreads();
        #pragma unroll
        for (int off = 256; off > 0; off >>= 1) { if (d < off) red[d] += red[d+off]; __syncthreads(); }
        float var = red[0] * (1.f/Dd);
        __syncthreads();
        float h = diff * rsqrtf(var + 1e-5f) * gg + bb;
        mem = BETA*mem + h;
        float s = (mem >= 1.0f) ? 1.f : 0.f;
        mem -= s;
        sp[rowoff + d] = __float2half_rn(s);
        cnt += s;
    }
    red[d] = cnt; __syncthreads();
    #pragma unroll
    for (int off = 256; off > 0; off >>= 1) { if (d < off) red[d] += red[d+off]; __syncthreads(); }
    if (d == 0) atomicAdd(counter, (unsigned long long)(red[0] + 0.5f));
}

// ---------------- LIF over time axis: fp32 src -> binary fp16 spikes ----------------
__global__ void lif_time_kernel(const float* __restrict__ src, __half* __restrict__ dst,
                                int inner_sz, float thr,
                                unsigned long long* __restrict__ counter) {
    long long total = (long long)Bb * inner_sz;
    long long idx = (long long)blockIdx.x*blockDim.x + threadIdx.x;
    int cnt = 0;
    if (idx < total) {
        long long b = idx / inner_sz, r = idx % inner_sz;
        const float* p = src + (size_t)b*Tt*inner_sz + r;
        __half* q = dst + (size_t)b*Tt*inner_sz + r;
        float mem = 0.f;
        #pragma unroll
        for (int t = 0; t < Tt; ++t) {
            float v2 = p[(size_t)t*inner_sz];
            mem = BETA*mem + v2;
            float s = (mem >= thr) ? 1.f : 0.f;
            q[(size_t)t*inner_sz] = __float2half_rn(s);
            mem -= s*thr;
            cnt += (int)s;
        }
    }
    #pragma unroll
    for (int off = 16; off; off >>= 1) cnt += __shfl_down_sync(0xffffffffu, cnt, off);
    if ((threadIdx.x & 31) == 0 && cnt) atomicAdd(counter, (unsigned long long)cnt);
}

// ---------------- fp16 MMA primitives ----------------
__device__ __forceinline__ uint32_t cvta_sh(const void* p) {
    return (uint32_t)__cvta_generic_to_shared(p);
}
__device__ __forceinline__ void ldsm4(uint32_t* r, uint32_t addr) {
    asm volatile("ldmatrix.sync.aligned.m8n8.x4.shared.b16 {%0,%1,%2,%3}, [%4];\n"
        : "=r"(r[0]), "=r"(r[1]), "=r"(r[2]), "=r"(r[3]) : "r"(addr));
}
__device__ __forceinline__ void ldsm4t(uint32_t* r, uint32_t addr) {
    asm volatile("ldmatrix.sync.aligned.m8n8.x4.trans.shared.b16 {%0,%1,%2,%3}, [%4];\n"
        : "=r"(r[0]), "=r"(r[1]), "=r"(r[2]), "=r"(r[3]) : "r"(addr));
}
__device__ __forceinline__ void mma16816(float* c, const uint32_t* a, const uint32_t* b) {
    asm volatile("mma.sync.aligned.m16n8k16.row.col.f32.f16.f16.f32 "
        "{%0,%1,%2,%3},{%4,%5,%6,%7},{%8,%9},{%0,%1,%2,%3};\n"
        : "+f"(c[0]), "+f"(c[1]), "+f"(c[2]), "+f"(c[3])
        : "r"(a[0]), "r"(a[1]), "r"(a[2]), "r"(a[3]), "r"(b[0]), "r"(b[1]));
}

// ---------------- generic split-fp16 MMA GEMM ----------------
// C = (Ahi@Bhi + 2^-11*(Ahi@Blo [+ Alo@Bhi])) * outscale [+ R]
// Block tile 128x64, BK=32, 256 threads (8 warps, 4x2).
// BT=true : B is k-major [K x N] row-major (standard GEMM), ldmatrix.trans
// BT=false: B is n-major [N x K] row-major (C = A@B^T, e.g. q@k^T), ldmatrix
template<bool HAS_ALO, bool BT, bool SPLIT_OUT, bool HAS_RES>
__global__ void __launch_bounds__(256, 2)
mma_gemm(const __half* __restrict__ Ah, const __half* __restrict__ Al,
         const __half* __restrict__ Bh, const __half* __restrict__ Bl,
         const float* __restrict__ R, float* __restrict__ Cf,
         __half* __restrict__ Ch, __half* __restrict__ Cl,
         int K, int lda, int ldb, int ldc,
         int zdiv,
         long long sA1, long long sA2,
         long long sB1, long long sB2,
         long long sC1, long long sC2,
         float outscale)
{
    __shared__ __half sA[2][128*40];
    __shared__ __half sB[2][2560];     // max(64*40, 32*72)

    int tid = threadIdx.x, lane = tid & 31, wid = tid >> 5;
    int wm = (wid & 3) * 32, wn = (wid >> 2) * 32;
    int bm0 = blockIdx.y * 128, bn0 = blockIdx.x * 64;
    int z = blockIdx.z, z1 = z / zdiv, z2 = z % zdiv;
    size_t aoff = (size_t)z1*sA1 + (size_t)z2*sA2;
    size_t boff = (size_t)z1*sB1 + (size_t)z2*sB2;
    size_t coff = (size_t)z1*sC1 + (size_t)z2*sC2;

    float acc0[2][4][4] = {};
    float acc1[2][4][4] = {};

    int ar = tid >> 2, ac = (tid & 3) << 3;   // A loader: 64 rows/pass, 8-half chunks

    for (int k0 = 0; k0 < K; k0 += 32) {
        // ---- load A tiles ----
        #pragma unroll
        for (int i = 0; i < 2; i++) {
            int row = ar + i*64;
            *(float4*)&sA[0][row*40 + ac] =
                *(const float4*)(Ah + aoff + (size_t)(bm0+row)*lda + k0 + ac);
            if (HAS_ALO)
                *(float4*)&sA[1][row*40 + ac] =
                    *(const float4*)(Al + aoff + (size_t)(bm0+row)*lda + k0 + ac);
        }
        // ---- load B tiles (hi+lo) ----
        if (BT) {
            int brk = tid >> 3, bck = (tid & 7) << 3;      // 32 x 64
            *(float4*)&sB[0][brk*72 + bck] =
                *(const float4*)(Bh + boff + (size_t)(k0+brk)*ldb + bn0 + bck);
            *(float4*)&sB[1][brk*72 + bck] =
                *(const float4*)(Bl + boff + (size_t)(k0+brk)*ldb + bn0 + bck);
        } else {
            int brk = tid >> 2, bck = (tid & 3) << 3;      // 64 x 32
            *(float4*)&sB[0][brk*40 + bck] =
                *(const float4*)(Bh + boff + (size_t)(bn0+brk)*ldb + k0 + bck);
            *(float4*)&sB[1][brk*40 + bck] =
                *(const float4*)(Bl + boff + (size_t)(bn0+brk)*ldb + k0 + bck);
        }
        __syncthreads();

        #pragma unroll
        for (int kk = 0; kk < 32; kk += 16) {
            uint32_t afh[2][4], afl[2][4];
            #pragma unroll
            for (int mi = 0; mi < 2; mi++) {
                int row = wm + mi*16 + (lane & 15);
                int col = kk + ((lane >> 4) << 3);
                ldsm4(afh[mi], cvta_sh(&sA[0][row*40 + col]));
                if (HAS_ALO) ldsm4(afl[mi], cvta_sh(&sA[1][row*40 + col]));
            }
            uint32_t bfh[2][4], bfl[2][4];
            int g = lane >> 3, rr = lane & 7;
            #pragma unroll
            for (int nh = 0; nh < 2; nh++) {
                if (BT) {
                    int krow = kk + (g & 1)*8 + rr;
                    int ncol = wn + nh*16 + (g >> 1)*8;
                    ldsm4t(bfh[nh], cvta_sh(&sB[0][krow*72 + ncol]));
                    ldsm4t(bfl[nh], cvta_sh(&sB[1][krow*72 + ncol]));
                } else {
                    int nrow = wn + nh*16 + (g >> 1)*8 + rr;
                    int kcol = kk + (g & 1)*8;
                    ldsm4(bfh[nh], cvta_sh(&sB[0][nrow*40 + kcol]));
                    ldsm4(bfl[nh], cvta_sh(&sB[1][nrow*40 + kcol]));
                }
            }
            #pragma unroll
            for (int mi = 0; mi < 2; mi++)
                #pragma unroll
                for (int nh = 0; nh < 2; nh++)
                    #pragma unroll
                    for (int s = 0; s < 2; s++) {
                        int nj = nh*2 + s;
                        mma16816(acc0[mi][nj], afh[mi], &bfh[nh][s*2]);
                        mma16816(acc1[mi][nj], afh[mi], &bfl[nh][s*2]);
                        if (HAS_ALO) mma16816(acc1[mi][nj], afl[mi], &bfh[nh][s*2]);
                    }
        }
        __syncthreads();
    }

    // ---- epilogue ----
    #pragma unroll
    for (int mi = 0; mi < 2; mi++)
        #pragma unroll
        for (int nj = 0; nj < 4; nj++) {
            int row0 = bm0 + wm + mi*16 + (lane >> 2);
            int col0 = bn0 + wn + nj*8 + ((lane & 3) << 1);
            #pragma unroll
            for (int e = 0; e < 4; e++) {
                int row = row0 + (e >> 1)*8;
                int col = col0 + (e & 1);
                float v = (acc0[mi][nj][e] + INV_LOSCALE*acc1[mi][nj][e]) * outscale;
                size_t off = coff + (size_t)row*ldc + col;
                if (HAS_RES) v += R[off];
                if (SPLIT_OUT) {
                    __half h = __float2half_rn(v);
                    Ch[off] = h;
                    Cl[off] = __float2half_rn((v - __half2float(h)) * LOSCALE);
                } else {
                    Cf[off] = v;
                }
            }
        }
}

// ---------------- write the 4 spike-rate scalars ----------------
__global__ void finalize_kernel(float* __restrict__ out, long long out_size) {
    if (out_size >= (long long)BTND + 4) {
        out[BTND+0] = (float)((double)g_cnt[0] / 4194304.0);   // r_lif1
        out[BTND+1] = (float)((double)g_cnt[1] / 16777216.0);  // r_attn
        out[BTND+2] = (float)((double)g_cnt[2] / 4194304.0);   // r_lif2
        out[BTND+3] = (float)((double)g_cnt[3] / 16777216.0);  // r_ffn
    }
}

// ---------------- host launcher ----------------
extern "C" void kernel_launch(void* const* d_in, const int* in_sizes, int n_in,
                              void* d_out, int out_size) {
    const float* x  = (const float*)d_in[0];
    const float* g1 = (const float*)d_in[1];
    const float* b1 = (const float*)d_in[2];
    const float* wq = (const float*)d_in[3];
    const float* wk = (const float*)d_in[4];
    const float* wv = (const float*)d_in[5];
    const float* wo = (const float*)d_in[6];
    const float* g2 = (const float*)d_in[7];
    const float* b2 = (const float*)d_in[8];
    const float* w1 = (const float*)d_in[9];
    const float* w2 = (const float*)d_in[10];
    float* out = (float*)d_out;

    __half *s1h, *qh, *ql, *kh, *kl, *vh, *vl, *sah, *aoh, *aol, *s2h, *hsh;
    __half *wqh,*wql,*wkh,*wkl,*wvh,*wvl,*woh,*wol,*w1h,*w1l,*w2h,*w2l;
    float *sc, *xm, *hid;
    unsigned long long* cnt;
    cudaGetSymbolAddress((void**)&s1h, g_s1h);
    cudaGetSymbolAddress((void**)&qh,  g_qh);  cudaGetSymbolAddress((void**)&ql, g_ql);
    cudaGetSymbolAddress((void**)&kh,  g_kh);  cudaGetSymbolAddress((void**)&kl, g_kl);
    cudaGetSymbolAddress((void**)&vh,  g_vh);  cudaGetSymbolAddress((void**)&vl, g_vl);
    cudaGetSymbolAddress((void**)&sc,  g_scores);
    cudaGetSymbolAddress((void**)&sah, g_sah);
    cudaGetSymbolAddress((void**)&aoh, g_aoh); cudaGetSymbolAddress((void**)&aol, g_aol);
    cudaGetSymbolAddress((void**)&xm,  g_xm);
    cudaGetSymbolAddress((void**)&s2h, g_s2h);
    cudaGetSymbolAddress((void**)&hid, g_hid);
    cudaGetSymbolAddress((void**)&hsh, g_hsh);
    cudaGetSymbolAddress((void**)&wqh, g_wqh); cudaGetSymbolAddress((void**)&wql, g_wql);
    cudaGetSymbolAddress((void**)&wkh, g_wkh); cudaGetSymbolAddress((void**)&wkl, g_wkl);
    cudaGetSymbolAddress((void**)&wvh, g_wvh); cudaGetSymbolAddress((void**)&wvl, g_wvl);
    cudaGetSymbolAddress((void**)&woh, g_woh); cudaGetSymbolAddress((void**)&wol, g_wol);
    cudaGetSymbolAddress((void**)&w1h, g_w1h); cudaGetSymbolAddress((void**)&w1l, g_w1l);
    cudaGetSymbolAddress((void**)&w2h, g_w2h); cudaGetSymbolAddress((void**)&w2l, g_w2l);
    cudaGetSymbolAddress((void**)&cnt, g_cnt);

    zero_cnt_kernel<<<1, 32>>>();

    // weight splits
    split_kernel<<<(Dd*Dd)/256,   256>>>(wq, wqh, wql, Dd*Dd);
    split_kernel<<<(Dd*Dd)/256,   256>>>(wk, wkh, wkl, Dd*Dd);
    split_kernel<<<(Dd*Dd)/256,   256>>>(wv, wvh, wvl, Dd*Dd);
    split_kernel<<<(Dd*Dd)/256,   256>>>(wo, woh, wol, Dd*Dd);
    split_kernel<<<(Dd*HIDd)/256, 256>>>(w1, w1h, w1l, Dd*HIDd);
    split_kernel<<<(HIDd*Dd)/256, 256>>>(w2, w2h, w2l, HIDd*Dd);

    // ---- attention branch ----
    ln_lif_kernel<<<Bb*Nn, 512>>>(x, g1, b1, s1h, cnt + 0);

    // QKV: binary A (s1), split B (weights), split outputs
    mma_gemm<false,true,true,false><<<dim3(Dd/64, BTN/128), 256>>>(
        s1h, nullptr, wqh, wql, nullptr, nullptr, qh, ql,
        Dd, Dd, Dd, Dd, 1, 0,0, 0,0, 0,0, 1.f);
    mma_gemm<false,true,true,false><<<dim3(Dd/64, BTN/128), 256>>>(
        s1h, nullptr, wkh, wkl, nullptr, nullptr, kh, kl,
        Dd, Dd, Dd, Dd, 1, 0,0, 0,0, 0,0, 1.f);
    mma_gemm<false,true,true,false><<<dim3(Dd/64, BTN/128), 256>>>(
        s1h, nullptr, wvh, wvl, nullptr, nullptr, vh, vl,
        Dd, Dd, Dd, Dd, 1, 0,0, 0,0, 0,0, 1.f);

    // scores = 0.125 * q @ k^T  (batched over B*T*H), 3-term split
    mma_gemm<true,false,false,false><<<dim3(Nn/64, Nn/128, Bb*Tt*Hh), 256>>>(
        qh, ql, kh, kl, nullptr, sc, nullptr, nullptr,
        DHh, Dd, Dd, Nn,
        Hh, (long long)Nn*Dd, 64LL, (long long)Nn*Dd, 64LL,
        (long long)Hh*Nn*Nn, (long long)Nn*Nn, 0.125f);

    lif_time_kernel<<<16384, 256>>>(sc, sah, Hh*Nn*Nn, 0.5f, cnt + 1);

    // attnout = sa @ v (batched), binary A, split B=v, split outputs
    mma_gemm<false,true,true,false><<<dim3(DHh/64, Nn/128, Bb*Tt*Hh), 256>>>(
        sah, nullptr, vh, vl, nullptr, nullptr, aoh, aol,
        Nn, Nn, Dd, Dd,
        Hh, (long long)Hh*Nn*Nn, (long long)Nn*Nn,
        (long long)Nn*Dd, 64LL, (long long)Nn*Dd, 64LL, 1.f);

    // xm = x + ao @ wo  (3-term)
    mma_gemm<true,true,false,true><<<dim3(Dd/64, BTN/128), 256>>>(
        aoh, aol, woh, wol, x, xm, nullptr, nullptr,
        Dd, Dd, Dd, Dd, 1, 0,0, 0,0, 0,0, 1.f);

    // ---- MLP branch ----
    ln_lif_kernel<<<Bb*Nn, 512>>>(xm, g2, b2, s2h, cnt + 2);

    // hid = s2 @ w1
    mma_gemm<false,true,false,false><<<dim3(HIDd/64, BTN/128), 256>>>(
        s2h, nullptr, w1h, w1l, nullptr, hid, nullptr, nullptr,
        Dd, Dd, HIDd, HIDd, 1, 0,0, 0,0, 0,0, 1.f);

    lif_time_kernel<<<16384, 256>>>(hid, hsh, Nn*HIDd, 1.0f, cnt + 3);

    // out = xm + hs @ w2
    mma_gemm<false,true,false,true><<<dim3(Dd/64, BTN/128), 256>>>(
        hsh, nullptr, w2h, w2l, xm, out, nullptr, nullptr,
        HIDd, HIDd, Dd, Dd, 1, 0,0, 0,0, 0,0, 1.f);

    finalize_kernel<<<1, 1>>>(out, (long long)out_size);
}

// round 5
// speedup vs baseline: 2.7683x; 1.1003x over previous
#include <cuda_runtime.h>
#include <cuda_fp16.h>
#include <cstdint>

// ---------------- problem dims ----------------
#define Bb   8
#define Tt   4
#define Nn   256
#define Dd   512
#define Hh   8
#define DHh  64
#define HIDd 2048
#define BTN  (Bb*Tt*Nn)            // 8192 rows
#define BTND ((size_t)BTN*Dd)      // 4194304
#define SCORES_ELEMS ((size_t)Bb*Tt*Hh*Nn*Nn)  // 16777216
#define HID_ELEMS    ((size_t)BTN*HIDd)        // 16777216

#define BETA 0.95122942450071403f  // fp32(exp(-1/20))
#define LOSCALE 2048.0f
#define INV_LOSCALE (1.0f/2048.0f)

// ---------------- scratch (static device globals; no allocation) ----------------
__device__ __half g_s1h[BTND];
__device__ __half g_qh[BTND], g_ql[BTND];
__device__ __half g_kh[BTND], g_kl[BTND];
__device__ __half g_vh[BTND], g_vl[BTND];
__device__ float  g_scores[SCORES_ELEMS];
__device__ __half g_sah[SCORES_ELEMS];
__device__ __half g_aoh[BTND], g_aol[BTND];
__device__ float  g_xm[BTND];
__device__ __half g_s2h[BTND];
__device__ float  g_hid[HID_ELEMS];
__device__ __half g_hsh[HID_ELEMS];
// weight splits
__device__ __half g_wqh[Dd*Dd], g_wql[Dd*Dd];
__device__ __half g_wkh[Dd*Dd], g_wkl[Dd*Dd];
__device__ __half g_wvh[Dd*Dd], g_wvl[Dd*Dd];
__device__ __half g_woh[Dd*Dd], g_wol[Dd*Dd];
__device__ __half g_w1h[Dd*HIDd], g_w1l[Dd*HIDd];
__device__ __half g_w2h[HIDd*Dd], g_w2l[HIDd*Dd];
__device__ unsigned long long g_cnt[4];

// ---------------- small helpers ----------------
__global__ void zero_cnt_kernel() {
    if (threadIdx.x < 4) g_cnt[threadIdx.x] = 0ULL;
}

__global__ void split_kernel(const float* __restrict__ src,
                             __half* __restrict__ hi, __half* __restrict__ lo, int n) {
    int i = blockIdx.x*blockDim.x + threadIdx.x;
    if (i < n) {
        float v = src[i];
        __half h = __float2half_rn(v);
        hi[i] = h;
        lo[i] = __float2half_rn((v - __half2float(h)) * LOSCALE);
    }
}

// ---------------- LayerNorm + LIF over time (per (b,n) row) ----------------
__global__ void ln_lif_kernel(const float* __restrict__ x,
                              const float* __restrict__ g,
                              const float* __restrict__ bia,
                              __half* __restrict__ sp,
                              unsigned long long* __restrict__ counter) {
    __shared__ float red[512];
    int bn = blockIdx.x;
    int b  = bn / Nn, n = bn % Nn;
    int d  = threadIdx.x;
    float gg = g[d], bb = bia[d];
    float mem = 0.f;
    float cnt = 0.f;
    for (int t = 0; t < Tt; ++t) {
        size_t rowoff = ((((size_t)b*Tt + t)*Nn) + n)*Dd;
        float v = x[rowoff + d];
        red[d] = v; __syncthreads();
        #pragma unroll
        for (int off = 256; off > 0; off >>= 1) { if (d < off) red[d] += red[d+off]; __syncthreads(); }
        float mean = red[0] * (1.f/Dd);
        __syncthreads();
        float diff = v - mean;
        red[d] = diff*diff; __syncthreads();
        #pragma unroll
        for (int off = 256; off > 0; off >>= 1) { if (d < off) red[d] += red[d+off]; __syncthreads(); }
        float var = red[0] * (1.f/Dd);
        __syncthreads();
        float h = diff * rsqrtf(var + 1e-5f) * gg + bb;
        mem = BETA*mem + h;
        float s = (mem >= 1.0f) ? 1.f : 0.f;
        mem -= s;
        sp[rowoff + d] = __float2half_rn(s);
        cnt += s;
    }
    red[d] = cnt; __syncthreads();
    #pragma unroll
    for (int off = 256; off > 0; off >>= 1) { if (d < off) red[d] += red[d+off]; __syncthreads(); }
    if (d == 0) atomicAdd(counter, (unsigned long long)(red[0] + 0.5f));
}

// ---------------- LIF over time axis: fp32 src -> binary fp16 spikes ----------------
__global__ void lif_time_kernel(const float* __restrict__ src, __half* __restrict__ dst,
                                int inner_sz, float thr,
                                unsigned long long* __restrict__ counter) {
    long long total = (long long)Bb * inner_sz;
    long long idx = (long long)blockIdx.x*blockDim.x + threadIdx.x;
    int cnt = 0;
    if (idx < total) {
        long long b = idx / inner_sz, r = idx % inner_sz;
        const float* p = src + (size_t)b*Tt*inner_sz + r;
        __half* q = dst + (size_t)b*Tt*inner_sz + r;
        float mem = 0.f;
        #pragma unroll
        for (int t = 0; t < Tt; ++t) {
            float v2 = p[(size_t)t*inner_sz];
            mem = BETA*mem + v2;
            float s = (mem >= thr) ? 1.f : 0.f;
            q[(size_t)t*inner_sz] = __float2half_rn(s);
            mem -= s*thr;
            cnt += (int)s;
        }
    }
    #pragma unroll
    for (int off = 16; off; off >>= 1) cnt += __shfl_down_sync(0xffffffffu, cnt, off);
    if ((threadIdx.x & 31) == 0 && cnt) atomicAdd(counter, (unsigned long long)cnt);
}

// ---------------- fp16 MMA primitives ----------------
__device__ __forceinline__ uint32_t cvta_sh(const void* p) {
    return (uint32_t)__cvta_generic_to_shared(p);
}
__device__ __forceinline__ void ldsm4(uint32_t* r, uint32_t addr) {
    asm volatile("ldmatrix.sync.aligned.m8n8.x4.shared.b16 {%0,%1,%2,%3}, [%4];\n"
        : "=r"(r[0]), "=r"(r[1]), "=r"(r[2]), "=r"(r[3]) : "r"(addr));
}
__device__ __forceinline__ void ldsm4t(uint32_t* r, uint32_t addr) {
    asm volatile("ldmatrix.sync.aligned.m8n8.x4.trans.shared.b16 {%0,%1,%2,%3}, [%4];\n"
        : "=r"(r[0]), "=r"(r[1]), "=r"(r[2]), "=r"(r[3]) : "r"(addr));
}
__device__ __forceinline__ void mma16816(float* c, const uint32_t* a, const uint32_t* b) {
    asm volatile("mma.sync.aligned.m16n8k16.row.col.f32.f16.f16.f32 "
        "{%0,%1,%2,%3},{%4,%5,%6,%7},{%8,%9},{%0,%1,%2,%3};\n"
        : "+f"(c[0]), "+f"(c[1]), "+f"(c[2]), "+f"(c[3])
        : "r"(a[0]), "r"(a[1]), "r"(a[2]), "r"(a[3]), "r"(b[0]), "r"(b[1]));
}
__device__ __forceinline__ void cp16(void* smem, const void* gmem) {
    asm volatile("cp.async.cg.shared.global [%0], [%1], 16;\n"
        :: "r"(cvta_sh(smem)), "l"(gmem));
}
#define CP_COMMIT() asm volatile("cp.async.commit_group;\n")
#define CP_WAIT0()  asm volatile("cp.async.wait_group 0;\n")

// ---------------- generic split-fp16 MMA GEMM, cp.async double-buffered ----------------
// C = (Ahi@Bhi + 2^-11*(Ahi@Blo [+ Alo@Bhi])) * outscale [+ R]
// Block tile 128x64, BK=32, 256 threads (8 warps, 4x2 warp grid).
// BT=true : B is k-major [K x N] row-major (standard GEMM), ldmatrix.trans
// BT=false: B is n-major [N x K] row-major (C = A@B^T), ldmatrix
template<bool HAS_ALO, bool BT, bool SPLIT_OUT, bool HAS_RES>
__global__ void __launch_bounds__(256)
mma_gemm(const __half* __restrict__ Ah, const __half* __restrict__ Al,
         const __half* __restrict__ Bh, const __half* __restrict__ Bl,
         const float* __restrict__ R, float* __restrict__ Cf,
         __half* __restrict__ Ch, __half* __restrict__ Cl,
         int K, int lda, int ldb, int ldc,
         int zdiv,
         long long sA1, long long sA2,
         long long sB1, long long sB2,
         long long sC1, long long sC2,
         float outscale)
{
    extern __shared__ __half sm[];
    constexpr int AH_SZ  = 128*40;                          // 5120 halves
    constexpr int A_SZ   = HAS_ALO ? 2*AH_SZ : AH_SZ;
    constexpr int B_SZ   = 2560;                            // per hi/lo tile
    constexpr int STAGE  = A_SZ + 2*B_SZ;

    int tid = threadIdx.x, lane = tid & 31, wid = tid >> 5;
    int wm = (wid & 3) * 32, wn = (wid >> 2) * 32;
    int bm0 = blockIdx.y * 128, bn0 = blockIdx.x * 64;
    int z = blockIdx.z, z1 = z / zdiv, z2 = z % zdiv;
    size_t aoff = (size_t)z1*sA1 + (size_t)z2*sA2;
    size_t boff = (size_t)z1*sB1 + (size_t)z2*sB2;
    size_t coff = (size_t)z1*sC1 + (size_t)z2*sC2;

    // loader indices
    int ar = tid >> 2, ac = (tid & 3) << 3;                 // A: 64 rows/pass, 8-half chunks
    int brkT = tid >> 3, bckT = (tid & 7) << 3;             // B (BT):  32 x 64
    int brkN = tid >> 2, bckN = (tid & 3) << 3;             // B (!BT): 64 x 32

    float acc0[2][4][4] = {};
    float acc1[2][4][4] = {};

    auto load_stage = [&](int k0, int st) {
        __half* base = sm + st*STAGE;
        #pragma unroll
        for (int i = 0; i < 2; i++) {
            int row = ar + i*64;
            cp16(&base[row*40 + ac],
                 Ah + aoff + (size_t)(bm0+row)*lda + k0 + ac);
            if (HAS_ALO)
                cp16(&base[AH_SZ + row*40 + ac],
                     Al + aoff + (size_t)(bm0+row)*lda + k0 + ac);
        }
        __half* sBh = base + A_SZ;
        __half* sBl = sBh + B_SZ;
        if (BT) {
            cp16(&sBh[brkT*72 + bckT], Bh + boff + (size_t)(k0+brkT)*ldb + bn0 + bckT);
            cp16(&sBl[brkT*72 + bckT], Bl + boff + (size_t)(k0+brkT)*ldb + bn0 + bckT);
        } else {
            cp16(&sBh[brkN*40 + bckN], Bh + boff + (size_t)(bn0+brkN)*ldb + k0 + bckN);
            cp16(&sBl[brkN*40 + bckN], Bl + boff + (size_t)(bn0+brkN)*ldb + k0 + bckN);
        }
        CP_COMMIT();
    };

    load_stage(0, 0);

    int st = 0;
    for (int k0 = 0; k0 < K; k0 += 32, st ^= 1) {
        CP_WAIT0();
        __syncthreads();
        if (k0 + 32 < K) load_stage(k0 + 32, st ^ 1);

        __half* base = sm + st*STAGE;
        __half* sAh = base;
        __half* sAl = base + AH_SZ;
        __half* sBh = base + A_SZ;
        __half* sBl = sBh + B_SZ;

        #pragma unroll
        for (int kk = 0; kk < 32; kk += 16) {
            uint32_t afh[2][4], afl[2][4];
            #pragma unroll
            for (int mi = 0; mi < 2; mi++) {
                int row = wm + mi*16 + (lane & 15);
                int col = kk + ((lane >> 4) << 3);
                ldsm4(afh[mi], cvta_sh(&sAh[row*40 + col]));
                if (HAS_ALO) ldsm4(afl[mi], cvta_sh(&sAl[row*40 + col]));
            }
            uint32_t bfh[2][4], bfl[2][4];
            int g = lane >> 3, rr = lane & 7;
            #pragma unroll
            for (int nh = 0; nh < 2; nh++) {
                if (BT) {
                    int krow = kk + (g & 1)*8 + rr;
                    int ncol = wn + nh*16 + (g >> 1)*8;
                    ldsm4t(bfh[nh], cvta_sh(&sBh[krow*72 + ncol]));
                    ldsm4t(bfl[nh], cvta_sh(&sBl[krow*72 + ncol]));
                } else {
                    int nrow = wn + nh*16 + (g >> 1)*8 + rr;
                    int kcol = kk + (g & 1)*8;
                    ldsm4(bfh[nh], cvta_sh(&sBh[nrow*40 + kcol]));
                    ldsm4(bfl[nh], cvta_sh(&sBl[nrow*40 + kcol]));
                }
            }
            #pragma unroll
            for (int mi = 0; mi < 2; mi++)
                #pragma unroll
                for (int nh = 0; nh < 2; nh++)
                    #pragma unroll
                    for (int s = 0; s < 2; s++) {
                        int nj = nh*2 + s;
                        mma16816(acc0[mi][nj], afh[mi], &bfh[nh][s*2]);
                        mma16816(acc1[mi][nj], afh[mi], &bfl[nh][s*2]);
                        if (HAS_ALO) mma16816(acc1[mi][nj], afl[mi], &bfh[nh][s*2]);
                    }
        }
        __syncthreads();
    }

    // ---- epilogue (vectorized pairs) ----
    #pragma unroll
    for (int mi = 0; mi < 2; mi++)
        #pragma unroll
        for (int nj = 0; nj < 4; nj++) {
            int row0 = bm0 + wm + mi*16 + (lane >> 2);
            int col0 = bn0 + wn + nj*8 + ((lane & 3) << 1);
            #pragma unroll
            for (int hh = 0; hh < 2; hh++) {
                int row = row0 + hh*8;
                size_t off = coff + (size_t)row*ldc + col0;
                float v0 = (acc0[mi][nj][hh*2+0] + INV_LOSCALE*acc1[mi][nj][hh*2+0]) * outscale;
                float v1 = (acc0[mi][nj][hh*2+1] + INV_LOSCALE*acc1[mi][nj][hh*2+1]) * outscale;
                if (HAS_RES) {
                    float2 r2 = *(const float2*)(R + off);
                    v0 += r2.x; v1 += r2.y;
                }
                if (SPLIT_OUT) {
                    __half h0 = __float2half_rn(v0), h1 = __float2half_rn(v1);
                    *(__half2*)(Ch + off) = __halves2half2(h0, h1);
                    *(__half2*)(Cl + off) = __halves2half2(
                        __float2half_rn((v0 - __half2float(h0)) * LOSCALE),
                        __float2half_rn((v1 - __half2float(h1)) * LOSCALE));
                } else {
                    *(float2*)(Cf + off) = make_float2(v0, v1);
                }
            }
        }
}

// ---------------- write the 4 spike-rate scalars ----------------
__global__ void finalize_kernel(float* __restrict__ out, long long out_size) {
    if (out_size >= (long long)BTND + 4) {
        out[BTND+0] = (float)((double)g_cnt[0] / 4194304.0);   // r_lif1
        out[BTND+1] = (float)((double)g_cnt[1] / 16777216.0);  // r_attn
        out[BTND+2] = (float)((double)g_cnt[2] / 4194304.0);   // r_lif2
        out[BTND+3] = (float)((double)g_cnt[3] / 16777216.0);  // r_ffn
    }
}

// ---------------- host launcher ----------------
extern "C" void kernel_launch(void* const* d_in, const int* in_sizes, int n_in,
                              void* d_out, int out_size) {
    const float* x  = (const float*)d_in[0];
    const float* g1 = (const float*)d_in[1];
    const float* b1 = (const float*)d_in[2];
    const float* wq = (const float*)d_in[3];
    const float* wk = (const float*)d_in[4];
    const float* wv = (const float*)d_in[5];
    const float* wo = (const float*)d_in[6];
    const float* g2 = (const float*)d_in[7];
    const float* b2 = (const float*)d_in[8];
    const float* w1 = (const float*)d_in[9];
    const float* w2 = (const float*)d_in[10];
    float* out = (float*)d_out;

    __half *s1h, *qh, *ql, *kh, *kl, *vh, *vl, *sah, *aoh, *aol, *s2h, *hsh;
    __half *wqh,*wql,*wkh,*wkl,*wvh,*wvl,*woh,*wol,*w1h,*w1l,*w2h,*w2l;
    float *sc, *xm, *hid;
    unsigned long long* cnt;
    cudaGetSymbolAddress((void**)&s1h, g_s1h);
    cudaGetSymbolAddress((void**)&qh,  g_qh);  cudaGetSymbolAddress((void**)&ql, g_ql);
    cudaGetSymbolAddress((void**)&kh,  g_kh);  cudaGetSymbolAddress((void**)&kl, g_kl);
    cudaGetSymbolAddress((void**)&vh,  g_vh);  cudaGetSymbolAddress((void**)&vl, g_vl);
    cudaGetSymbolAddress((void**)&sc,  g_scores);
    cudaGetSymbolAddress((void**)&sah, g_sah);
    cudaGetSymbolAddress((void**)&aoh, g_aoh); cudaGetSymbolAddress((void**)&aol, g_aol);
    cudaGetSymbolAddress((void**)&xm,  g_xm);
    cudaGetSymbolAddress((void**)&s2h, g_s2h);
    cudaGetSymbolAddress((void**)&hid, g_hid);
    cudaGetSymbolAddress((void**)&hsh, g_hsh);
    cudaGetSymbolAddress((void**)&wqh, g_wqh); cudaGetSymbolAddress((void**)&wql, g_wql);
    cudaGetSymbolAddress((void**)&wkh, g_wkh); cudaGetSymbolAddress((void**)&wkl, g_wkl);
    cudaGetSymbolAddress((void**)&wvh, g_wvh); cudaGetSymbolAddress((void**)&wvl, g_wvl);
    cudaGetSymbolAddress((void**)&woh, g_woh); cudaGetSymbolAddress((void**)&wol, g_wol);
    cudaGetSymbolAddress((void**)&w1h, g_w1h); cudaGetSymbolAddress((void**)&w1l, g_w1l);
    cudaGetSymbolAddress((void**)&w2h, g_w2h); cudaGetSymbolAddress((void**)&w2l, g_w2l);
    cudaGetSymbolAddress((void**)&cnt, g_cnt);

    // dynamic smem sizes (halves -> bytes): ALO: (2*5120+5120)*2*2 ; else (5120+5120)*2*2
    const int SMEM_ALO  = (2*(128*40) + 2*2560) * 2 * 2;   // 61440 B
    const int SMEM_NALO = ((128*40)  + 2*2560) * 2 * 2;    // 40960 B

    cudaFuncSetAttribute(mma_gemm<false,true ,true ,false>, cudaFuncAttributeMaxDynamicSharedMemorySize, SMEM_NALO);
    cudaFuncSetAttribute(mma_gemm<true ,false,false,false>, cudaFuncAttributeMaxDynamicSharedMemorySize, SMEM_ALO);
    cudaFuncSetAttribute(mma_gemm<true ,true ,false,true >, cudaFuncAttributeMaxDynamicSharedMemorySize, SMEM_ALO);
    cudaFuncSetAttribute(mma_gemm<false,true ,false,false>, cudaFuncAttributeMaxDynamicSharedMemorySize, SMEM_NALO);
    cudaFuncSetAttribute(mma_gemm<false,true ,false,true >, cudaFuncAttributeMaxDynamicSharedMemorySize, SMEM_NALO);

    zero_cnt_kernel<<<1, 32>>>();

    // weight splits
    split_kernel<<<(Dd*Dd)/256,   256>>>(wq, wqh, wql, Dd*Dd);
    split_kernel<<<(Dd*Dd)/256,   256>>>(wk, wkh, wkl, Dd*Dd);
    split_kernel<<<(Dd*Dd)/256,   256>>>(wv, wvh, wvl, Dd*Dd);
    split_kernel<<<(Dd*Dd)/256,   256>>>(wo, woh, wol, Dd*Dd);
    split_kernel<<<(Dd*HIDd)/256, 256>>>(w1, w1h, w1l, Dd*HIDd);
    split_kernel<<<(HIDd*Dd)/256, 256>>>(w2, w2h, w2l, HIDd*Dd);

    // ---- attention branch ----
    ln_lif_kernel<<<Bb*Nn, 512>>>(x, g1, b1, s1h, cnt + 0);

    // QKV: binary A (s1), split B (weights), split outputs
    mma_gemm<false,true,true,false><<<dim3(Dd/64, BTN/128), 256, SMEM_NALO>>>(
        s1h, nullptr, wqh, wql, nullptr, nullptr, qh, ql,
        Dd, Dd, Dd, Dd, 1, 0,0, 0,0, 0,0, 1.f);
    mma_gemm<false,true,true,false><<<dim3(Dd/64, BTN/128), 256, SMEM_NALO>>>(
        s1h, nullptr, wkh, wkl, nullptr, nullptr, kh, kl,
        Dd, Dd, Dd, Dd, 1, 0,0, 0,0, 0,0, 1.f);
    mma_gemm<false,true,true,false><<<dim3(Dd/64, BTN/128), 256, SMEM_NALO>>>(
        s1h, nullptr, wvh, wvl, nullptr, nullptr, vh, vl,
        Dd, Dd, Dd, Dd, 1, 0,0, 0,0, 0,0, 1.f);

    // scores = 0.125 * q @ k^T  (batched over B*T*H), 3-term split
    mma_gemm<true,false,false,false><<<dim3(Nn/64, Nn/128, Bb*Tt*Hh), 256, SMEM_ALO>>>(
        qh, ql, kh, kl, nullptr, sc, nullptr, nullptr,
        DHh, Dd, Dd, Nn,
        Hh, (long long)Nn*Dd, 64LL, (long long)Nn*Dd, 64LL,
        (long long)Hh*Nn*Nn, (long long)Nn*Nn, 0.125f);

    lif_time_kernel<<<16384, 256>>>(sc, sah, Hh*Nn*Nn, 0.5f, cnt + 1);

    // attnout = sa @ v (batched), binary A, split B=v, split outputs
    mma_gemm<false,true,true,false><<<dim3(DHh/64, Nn/128, Bb*Tt*Hh), 256, SMEM_NALO>>>(
        sah, nullptr, vh, vl, nullptr, nullptr, aoh, aol,
        Nn, Nn, Dd, Dd,
        Hh, (long long)Hh*Nn*Nn, (long long)Nn*Nn,
        (long long)Nn*Dd, 64LL, (long long)Nn*Dd, 64LL, 1.f);

    // xm = x + ao @ wo  (3-term)
    mma_gemm<true,true,false,true><<<dim3(Dd/64, BTN/128), 256, SMEM_ALO>>>(
        aoh, aol, woh, wol, x, xm, nullptr, nullptr,
        Dd, Dd, Dd, Dd, 1, 0,0, 0,0, 0,0, 1.f);

    // ---- MLP branch ----
    ln_lif_kernel<<<Bb*Nn, 512>>>(xm, g2, b2, s2h, cnt + 2);

    // hid = s2 @ w1
    mma_gemm<false,true,false,false><<<dim3(HIDd/64, BTN/128), 256, SMEM_NALO>>>(
        s2h, nullptr, w1h, w1l, nullptr, hid, nullptr, nullptr,
        Dd, Dd, HIDd, HIDd, 1, 0,0, 0,0, 0,0, 1.f);

    lif_time_kernel<<<16384, 256>>>(hid, hsh, Nn*HIDd, 1.0f, cnt + 3);

    // out = xm + hs @ w2
    mma_gemm<false,true,false,true><<<dim3(Dd/64, BTN/128), 256, SMEM_NALO>>>(
        hsh, nullptr, w2h, w2l, xm, out, nullptr, nullptr,
        HIDd, HIDd, Dd, Dd, 1, 0,0, 0,0, 0,0, 1.f);

    finalize_kernel<<<1, 1>>>(out, (long long)out_size);
}